// round 1
// baseline (speedup 1.0000x reference)
#include <cuda_runtime.h>
#include <cuda_bf16.h>

// ---------------------------------------------------------------------------
// GCNArchEmbedder: algebraically collapsed.
//   out[row] = ( (1/4) * sum_j m[j] * relu(sum_k adjcoef * h1[k]) ) @ W2
// with h1 rows built from precomputed tables U0/U1/Uc/H1init.
// row = b*2+g, ROWS = 65536. Final GEMM [65536x128]@[128x128] in fp32 via
// packed fma.rn.f32x2 (FFMA2).
// ---------------------------------------------------------------------------

#define NUM_PRIM   8
#define OPD        48
#define OPH        48
#define GD         128
#define ROWS       65536      // BATCH * NUM_CELL_GROUPS
#define TILE_M     64
#define TPAD       132        // padded k-stride for smem rows

// table rows: 0..7 U0[p], 8..15 U1[p], 16..17 H1init, 18 Uc   (each 128 wide)
__device__ float g_tab[19 * GD];

// ---------------------------------------------------------------------------
// Precompute kernel (tiny): builds g_tab from weights. <<<1,128>>>
// ---------------------------------------------------------------------------
__global__ void gcn_precompute_kernel(const float* __restrict__ init_emb,  // (2,96)
                                      const float* __restrict__ op_emb,    // (8,48)
                                      const float* __restrict__ xw,        // (96,48)
                                      const float* __restrict__ xb,        // (48)
                                      const float* __restrict__ w1)        // (48,128)
{
    __shared__ float T0[NUM_PRIM][OPH];
    __shared__ float T1[NUM_PRIM][OPH];
    __shared__ float yin[2][OPH];

    int t = threadIdx.x;
    if (t < OPH) {
        int h = t;
        for (int p = 0; p < NUM_PRIM; p++) {
            float s0 = 0.f, s1 = 0.f;
            for (int d = 0; d < OPD; d++) {
                float e = op_emb[p * OPD + d];
                s0 = fmaf(e, xw[d * OPH + h], s0);
                s1 = fmaf(e, xw[(OPD + d) * OPH + h], s1);
            }
            T0[p][h] = s0;
            T1[p][h] = s1;
        }
        for (int k = 0; k < 2; k++) {
            float s = xb[h];
            for (int d = 0; d < 2 * OPD; d++)
                s = fmaf(init_emb[k * 2 * OPD + d], xw[d * OPH + h], s);
            yin[k][h] = s;
        }
    }
    __syncthreads();

    int f = t;  // 0..127
    {
        float sc = 0.f;
        for (int h = 0; h < OPH; h++) sc = fmaf(xb[h], w1[h * GD + f], sc);
        g_tab[18 * GD + f] = sc;

        for (int p = 0; p < NUM_PRIM; p++) {
            float s0 = 0.f, s1 = 0.f;
            for (int h = 0; h < OPH; h++) {
                float w = w1[h * GD + f];
                s0 = fmaf(T0[p][h], w, s0);
                s1 = fmaf(T1[p][h], w, s1);
            }
            g_tab[p * GD + f] = s0;
            g_tab[(8 + p) * GD + f] = s1;
        }
        for (int k = 0; k < 2; k++) {
            float s = 0.f;
            for (int h = 0; h < OPH; h++) s = fmaf(yin[k][h], w1[h * GD + f], s);
            g_tab[(16 + k) * GD + f] = s;
        }
    }
}

// ---------------------------------------------------------------------------
// Main kernel
// smem layout (floats):
//   Wp     [0      , 16384)   W2 paired by k: Wp[k2][2f+parity]
//   S      [16384  , 24832)   64 x TPAD
//   tab    [24832  , 27340)   19 x TPAD
//   archsm [27340  , 28364)   64 x 16 ints
// total 28364 floats = 113456 B
// ---------------------------------------------------------------------------
#define SMEM_FLOATS 28364
#define SMEM_BYTES  (SMEM_FLOATS * 4)

__device__ __forceinline__ void fma2(unsigned long long& d,
                                     unsigned long long a,
                                     unsigned long long b) {
    asm("fma.rn.f32x2 %0, %1, %2, %0;" : "+l"(d) : "l"(a), "l"(b));
}

__device__ __forceinline__ float pairsum(unsigned long long v) {
    float lo = __uint_as_float((unsigned int)(v & 0xffffffffULL));
    float hi = __uint_as_float((unsigned int)(v >> 32));
    return lo + hi;
}

__global__ void __launch_bounds__(256, 2)
gcn_main_kernel(const int* __restrict__ archs,   // (ROWS, 16): 8 prev + 8 op
                const float* __restrict__ w2,    // (128,128)
                float* __restrict__ out)         // (ROWS, 128)
{
    extern __shared__ float sm[];
    float* Wp  = sm;
    float* S   = sm + 16384;
    float* tab = sm + 24832;
    int*  archsm = (int*)(sm + 27340);

    const int tid = threadIdx.x;
    const int rowbase = blockIdx.x * TILE_M;

    // --- stage tables into smem (padded) ---
    for (int idx = tid; idx < 19 * GD; idx += 256) {
        tab[(idx >> 7) * TPAD + (idx & 127)] = g_tab[idx];
    }
    // --- stage W2 in k-paired layout ---
    {
        const float4* W2v = (const float4*)w2;
        for (int idx = tid; idx < 4096; idx += 256) {
            int k  = idx >> 5;
            int f0 = (idx & 31) << 2;
            float4 v = W2v[idx];
            float* dst = Wp + (k >> 1) * 256 + 2 * f0 + (k & 1);
            dst[0] = v.x; dst[2] = v.y; dst[4] = v.z; dst[6] = v.w;
        }
    }
    // --- stage arch ints: 64 rows * 16 ints = 256 int4 ---
    {
        const int4* av = (const int4*)archs + (size_t)rowbase * 4;
        ((int4*)archsm)[tid] = av[tid];
    }
    __syncthreads();

    // =======================================================================
    // Phase 1: build S[row][k] = 0.25 * sum_s m[s] * relu(sum_j A[s][j]*h1[j])
    // 4 threads per row, k strided by 4.
    // =======================================================================
    {
        const int row = tid >> 2;
        const int kq  = tid & 3;
        const int* ar = archsm + row * 16;

        int pe[8], oe[8];
#pragma unroll
        for (int e = 0; e < 8; e++) { pe[e] = ar[e]; oe[e] = ar[8 + e]; }

        float A[4][6];
        float mm[4];
#pragma unroll
        for (int s = 0; s < 4; s++) {
#pragma unroll
            for (int j = 0; j < 6; j++)
                A[s][j] = (pe[2 * s] == j ? 1.f : 0.f) + (pe[2 * s + 1] == j ? 1.f : 0.f);
            float c = 0.f;
#pragma unroll
            for (int e = 0; e < 8; e++) c += (pe[e] == s + 2) ? 1.f : 0.f;
            mm[s] = c * 0.25f;  // fold the mean(1/4)
        }

        const float* tU0 = tab;
        const float* tU1 = tab + 8 * TPAD;
        const float* tH  = tab + 16 * TPAD;
        const float* tC  = tab + 18 * TPAD;
        float* Srow = S + row * TPAD;

#pragma unroll 4
        for (int i = 0; i < 32; i++) {
            int k = kq + (i << 2);
            float c  = tC[k];
            float h0 = tH[k];
            float h1 = tH[TPAD + k];
            float h2 = tU0[oe[0] * TPAD + k] + tU1[oe[1] * TPAD + k] + c;
            float h3 = tU0[oe[2] * TPAD + k] + tU1[oe[3] * TPAD + k] + c;
            float h4 = tU0[oe[4] * TPAD + k] + tU1[oe[5] * TPAD + k] + c;
            float h5 = tU0[oe[6] * TPAD + k] + tU1[oe[7] * TPAD + k] + c;
            float acc = 0.f;
#pragma unroll
            for (int s = 0; s < 4; s++) {
                float z = A[s][0] * h0;
                z = fmaf(A[s][1], h1, z);
                z = fmaf(A[s][2], h2, z);
                z = fmaf(A[s][3], h3, z);
                z = fmaf(A[s][4], h4, z);
                z = fmaf(A[s][5], h5, z);
                z = fmaxf(z, 0.f);
                acc = fmaf(mm[s], z, acc);
            }
            Srow[k] = acc;
        }
    }
    __syncthreads();

    // =======================================================================
    // Phase 2: out[tile] = S @ W2, fp32 packed FFMA2.
    // Thread (rg, lane): rows rg*8..+7, cols lane*4..+3.
    // acc packs (even-k, odd-k) partial sums.
    // =======================================================================
    {
        const int lane = tid & 31;
        const int rg   = tid >> 5;
        const float* Sb = S + rg * 8 * TPAD;
        const float* Wl = Wp + lane * 8;

        unsigned long long acc[8][4];
#pragma unroll
        for (int i = 0; i < 8; i++)
#pragma unroll
            for (int j = 0; j < 4; j++) acc[i][j] = 0ULL;

        for (int k2 = 0; k2 < 64; k2 += 2) {
            const float* wr = Wl + k2 * 256;
            ulonglong2 bA0 = *(const ulonglong2*)(wr);
            ulonglong2 bA1 = *(const ulonglong2*)(wr + 4);
            ulonglong2 bB0 = *(const ulonglong2*)(wr + 256);
            ulonglong2 bB1 = *(const ulonglong2*)(wr + 260);
#pragma unroll
            for (int i = 0; i < 8; i++) {
                ulonglong2 a = *(const ulonglong2*)(Sb + i * TPAD + 2 * k2);
                fma2(acc[i][0], a.x, bA0.x);
                fma2(acc[i][1], a.x, bA0.y);
                fma2(acc[i][2], a.x, bA1.x);
                fma2(acc[i][3], a.x, bA1.y);
                fma2(acc[i][0], a.y, bB0.x);
                fma2(acc[i][1], a.y, bB0.y);
                fma2(acc[i][2], a.y, bB1.x);
                fma2(acc[i][3], a.y, bB1.y);
            }
        }

        float* ob = out + (size_t)rowbase * GD + lane * 4;
#pragma unroll
        for (int i = 0; i < 8; i++) {
            float4 v;
            v.x = pairsum(acc[i][0]);
            v.y = pairsum(acc[i][1]);
            v.z = pairsum(acc[i][2]);
            v.w = pairsum(acc[i][3]);
            *(float4*)(ob + (size_t)(rg * 8 + i) * GD) = v;
        }
    }
}

// ---------------------------------------------------------------------------
extern "C" void kernel_launch(void* const* d_in, const int* in_sizes, int n_in,
                              void* d_out, int out_size) {
    const int*   archs    = (const int*)  d_in[0];
    const float* init_emb = (const float*)d_in[1];
    const float* op_emb   = (const float*)d_in[2];
    const float* xw       = (const float*)d_in[3];
    const float* xb       = (const float*)d_in[4];
    const float* w1       = (const float*)d_in[5];
    const float* w2       = (const float*)d_in[6];
    float* out = (float*)d_out;

    cudaFuncSetAttribute(gcn_main_kernel,
                         cudaFuncAttributeMaxDynamicSharedMemorySize, SMEM_BYTES);

    gcn_precompute_kernel<<<1, 128>>>(init_emb, op_emb, xw, xb, w1);
    gcn_main_kernel<<<ROWS / TILE_M, 256, SMEM_BYTES>>>(archs, w2, out);
}

// round 3
// speedup vs baseline: 1.6774x; 1.6774x over previous
#include <cuda_runtime.h>
#include <cuda_bf16.h>
#include <cstdint>

// ---------------------------------------------------------------------------
// GCNArchEmbedder via mma.sync bf16 (HMMA), 3-pass hi/lo fp32 emulation.
//   Phase 1: S[row][k] from precomputed tables (fp32, smem).
//   Phase 2: D = S @ W2 as Ahi*Bhi + Ahi*Blo + Alo*Bhi with m16n8k16 bf16 mma.
//   B is pre-packed into per-lane fragment layout (one LDS.64 per frag).
// ---------------------------------------------------------------------------

#define NUM_PRIM   8
#define OPD        48
#define OPH        48
#define GD         128
#define ROWS       65536
#define TILE_M     128
#define TPAD       132

// table rows: 0..7 U0[p], 8..15 U1[p], 16..17 H1init, 18 Uc (each 128 wide)
__device__ float g_tab[19 * GD];
// W2 bf16 hi/lo, fragment-packed: index = (ks*16 + ntile)*32 + lane
__device__ __align__(16) uint2 g_bhi[4096];
__device__ __align__(16) uint2 g_blo[4096];

typedef unsigned long long ull;
__device__ __forceinline__ ull pk2(float lo, float hi) {
    ull r; asm("mov.b64 %0, {%1, %2};" : "=l"(r) : "f"(lo), "f"(hi)); return r;
}
__device__ __forceinline__ void unpk2(float& lo, float& hi, ull v) {
    asm("mov.b64 {%0, %1}, %2;" : "=f"(lo), "=f"(hi) : "l"(v));
}
__device__ __forceinline__ ull add2(ull a, ull b) {
    ull r; asm("add.rn.f32x2 %0, %1, %2;" : "=l"(r) : "l"(a), "l"(b)); return r;
}
__device__ __forceinline__ ull mul2(ull a, ull b) {
    ull r; asm("mul.rn.f32x2 %0, %1, %2;" : "=l"(r) : "l"(a), "l"(b)); return r;
}
__device__ __forceinline__ void fma2(ull& d, ull a, ull b) {
    asm("fma.rn.f32x2 %0, %1, %2, %0;" : "+l"(d) : "l"(a), "l"(b));
}
// low half = first arg (k-even element)
__device__ __forceinline__ uint32_t bf16x2(float lo, float hi) {
    uint32_t r; asm("cvt.rn.bf16x2.f32 %0, %1, %2;" : "=r"(r) : "f"(hi), "f"(lo)); return r;
}
__device__ __forceinline__ float bf_lo(uint32_t u) { return __uint_as_float(u << 16); }
__device__ __forceinline__ float bf_hi(uint32_t u) { return __uint_as_float(u & 0xffff0000u); }

__device__ __forceinline__ void mma_bf16(float* d, const uint32_t* a, uint2 b) {
    asm volatile(
        "mma.sync.aligned.m16n8k16.row.col.f32.bf16.bf16.f32 "
        "{%0,%1,%2,%3}, {%4,%5,%6,%7}, {%8,%9}, {%0,%1,%2,%3};"
        : "+f"(d[0]), "+f"(d[1]), "+f"(d[2]), "+f"(d[3])
        : "r"(a[0]), "r"(a[1]), "r"(a[2]), "r"(a[3]), "r"(b.x), "r"(b.y));
}

// ---------------------------------------------------------------------------
// Precompute 1: tables. <<<1,128>>>
// ---------------------------------------------------------------------------
__global__ void gcn_precompute_kernel(const float* __restrict__ init_emb,
                                      const float* __restrict__ op_emb,
                                      const float* __restrict__ xw,
                                      const float* __restrict__ xb,
                                      const float* __restrict__ w1) {
    __shared__ float T0[NUM_PRIM][OPH];
    __shared__ float T1[NUM_PRIM][OPH];
    __shared__ float yin[2][OPH];
    int t = threadIdx.x;
    if (t < OPH) {
        int h = t;
        for (int p = 0; p < NUM_PRIM; p++) {
            float s0 = 0.f, s1 = 0.f;
            for (int d = 0; d < OPD; d++) {
                float e = op_emb[p * OPD + d];
                s0 = fmaf(e, xw[d * OPH + h], s0);
                s1 = fmaf(e, xw[(OPD + d) * OPH + h], s1);
            }
            T0[p][h] = s0; T1[p][h] = s1;
        }
        for (int k = 0; k < 2; k++) {
            float s = xb[h];
            for (int d = 0; d < 2 * OPD; d++)
                s = fmaf(init_emb[k * 2 * OPD + d], xw[d * OPH + h], s);
            yin[k][h] = s;
        }
    }
    __syncthreads();
    int f = t;
    float sc = 0.f;
    for (int h = 0; h < OPH; h++) sc = fmaf(xb[h], w1[h * GD + f], sc);
    g_tab[18 * GD + f] = sc;
    for (int p = 0; p < NUM_PRIM; p++) {
        float s0 = 0.f, s1 = 0.f;
        for (int h = 0; h < OPH; h++) {
            float w = w1[h * GD + f];
            s0 = fmaf(T0[p][h], w, s0);
            s1 = fmaf(T1[p][h], w, s1);
        }
        g_tab[p * GD + f] = s0;
        g_tab[(8 + p) * GD + f] = s1;
    }
    for (int k = 0; k < 2; k++) {
        float s = 0.f;
        for (int h = 0; h < OPH; h++) s = fmaf(yin[k][h], w1[h * GD + f], s);
        g_tab[(16 + k) * GD + f] = s;
    }
}

// ---------------------------------------------------------------------------
// Precompute 2: pack W2 into bf16 hi/lo mma B-fragments. <<<16,256>>>
// B frag (m16n8k16, col): b0: k=(l%4)*2+{0,1}, n=l/4 ; b1: k+8.
// ---------------------------------------------------------------------------
__global__ void w2_pack_kernel(const float* __restrict__ w2) {
    int idx = blockIdx.x * 256 + threadIdx.x;   // 0..4095
    int lane = idx & 31;
    int nt   = (idx >> 5) & 15;
    int ks   = idx >> 9;
    int k0 = ks * 16 + (lane & 3) * 2;
    int n  = nt * 8 + (lane >> 2);
    float w00 = w2[k0 * GD + n];
    float w01 = w2[(k0 + 1) * GD + n];
    float w10 = w2[(k0 + 8) * GD + n];
    float w11 = w2[(k0 + 9) * GD + n];
    uint32_t b0h = bf16x2(w00, w01);
    uint32_t b1h = bf16x2(w10, w11);
    uint32_t b0l = bf16x2(w00 - bf_lo(b0h), w01 - bf_hi(b0h));
    uint32_t b1l = bf16x2(w10 - bf_lo(b1h), w11 - bf_hi(b1h));
    g_bhi[idx] = make_uint2(b0h, b1h);
    g_blo[idx] = make_uint2(b0l, b1l);
}

// ---------------------------------------------------------------------------
// Main kernel. smem byte layout:
//   S    0       (128*132*4 = 67584)
//   tab  67584   (19*132*4  = 10032)
//   Bhi  77632   (32768)
//   Blo  110400  (32768)
//   arch 143168  (8192)
// total 151360 B
// ---------------------------------------------------------------------------
#define SM_S     0
#define SM_TAB   67584
#define SM_BHI   77632
#define SM_BLO   110400
#define SM_ARCH  143168
#define SMEM_BYTES 151360

__global__ void __launch_bounds__(512, 1)
gcn_main_kernel(const int* __restrict__ archs, float* __restrict__ out) {
    extern __shared__ char smem[];
    float* S    = (float*)(smem + SM_S);
    float* tab  = (float*)(smem + SM_TAB);
    uint2* Bhi  = (uint2*)(smem + SM_BHI);
    uint2* Blo  = (uint2*)(smem + SM_BLO);
    int*  archsm = (int*)(smem + SM_ARCH);

    const int tid  = threadIdx.x;
    const int wid  = tid >> 5;
    const int lane = tid & 31;
    const int rowbase = blockIdx.x * TILE_M;

    // ---- stage B frags, tables, archs ----
    {
        const int4* sh = (const int4*)g_bhi;
        const int4* sl = (const int4*)g_blo;
        int4* dh = (int4*)Bhi;
        int4* dl = (int4*)Blo;
#pragma unroll
        for (int i = 0; i < 4; i++) {
            dh[tid + 512 * i] = sh[tid + 512 * i];
            dl[tid + 512 * i] = sl[tid + 512 * i];
        }
        for (int idx = tid; idx < 19 * GD; idx += 512)
            tab[(idx >> 7) * TPAD + (idx & 127)] = g_tab[idx];
        const int4* av = (const int4*)archs + (size_t)rowbase * 4;
        ((int4*)archsm)[tid] = av[tid];
    }
    __syncthreads();

    // =======================================================================
    // Phase 1: S[row][k] = 0.25 * sum_s m_s * relu(sum_j A_sj h_j[k])
    // thread = (row, k-quarter); 16 k-pair iters each.
    // =======================================================================
    {
        const int row = tid & 127;
        const int kq  = tid >> 7;          // 0..3
        const int kbase = kq << 5;
        const int* ar = archsm + row * 16;
        int pe[8], oe[8];
#pragma unroll
        for (int e = 0; e < 8; e++) { pe[e] = ar[e]; oe[e] = ar[8 + e]; }

        ull A2[4][6];
        float mmv[4];
#pragma unroll
        for (int s = 0; s < 4; s++) {
#pragma unroll
            for (int j = 0; j < 6; j++) {
                float v = (pe[2 * s] == j ? 1.f : 0.f) + (pe[2 * s + 1] == j ? 1.f : 0.f);
                A2[s][j] = pk2(v, v);
            }
            float c = 0.f;
#pragma unroll
            for (int e = 0; e < 8; e++) c += (pe[e] == s + 2) ? 1.f : 0.f;
            mmv[s] = c * 0.25f;
        }

        const float* qa0 = tab + oe[0] * TPAD;
        const float* qb0 = tab + (8 + oe[1]) * TPAD;
        const float* qa1 = tab + oe[2] * TPAD;
        const float* qb1 = tab + (8 + oe[3]) * TPAD;
        const float* qa2 = tab + oe[4] * TPAD;
        const float* qb2 = tab + (8 + oe[5]) * TPAD;
        const float* qa3 = tab + oe[6] * TPAD;
        const float* qb3 = tab + (8 + oe[7]) * TPAD;
        const float* p0 = tab + 16 * TPAD;
        const float* p1 = tab + 17 * TPAD;
        const float* pc = tab + 18 * TPAD;
        float* Srow = S + row * TPAD;

#pragma unroll 4
        for (int i = 0; i < 16; i++) {
            const int k = kbase + 2 * i;
            ull c  = *(const ull*)(pc + k);
            ull h0 = *(const ull*)(p0 + k);
            ull h1 = *(const ull*)(p1 + k);
            ull h2 = add2(add2(*(const ull*)(qa0 + k), *(const ull*)(qb0 + k)), c);
            ull h3 = add2(add2(*(const ull*)(qa1 + k), *(const ull*)(qb1 + k)), c);
            ull h4 = add2(add2(*(const ull*)(qa2 + k), *(const ull*)(qb2 + k)), c);
            ull h5 = add2(add2(*(const ull*)(qa3 + k), *(const ull*)(qb3 + k)), c);
            float a0 = 0.f, a1 = 0.f;
#pragma unroll
            for (int s = 0; s < 4; s++) {
                ull z = mul2(A2[s][0], h0);
                fma2(z, A2[s][1], h1);
                fma2(z, A2[s][2], h2);
                fma2(z, A2[s][3], h3);
                fma2(z, A2[s][4], h4);
                fma2(z, A2[s][5], h5);
                float zl, zh; unpk2(zl, zh, z);
                zl = fmaxf(zl, 0.f);
                zh = fmaxf(zh, 0.f);
                a0 = fmaf(mmv[s], zl, a0);
                a1 = fmaf(mmv[s], zh, a1);
            }
            *(float2*)(Srow + k) = make_float2(a0, a1);
        }
    }
    __syncthreads();

    // =======================================================================
    // Phase 2: warp (rg, cg) computes rows [32rg,32rg+32) x cols [32cg,32cg+32)
    // via m16n8k16 bf16 mma, 3 passes (Ahi*Bhi + Ahi*Blo + Alo*Bhi).
    // =======================================================================
    {
        const int rg = wid >> 2;
        const int cg = wid & 3;
        float acc[2][4][4];
#pragma unroll
        for (int m = 0; m < 2; m++)
#pragma unroll
            for (int nt = 0; nt < 4; nt++)
#pragma unroll
                for (int j = 0; j < 4; j++) acc[m][nt][j] = 0.f;

#pragma unroll
        for (int ks = 0; ks < 8; ks++) {
            uint32_t ahi[2][4], alo[2][4];
#pragma unroll
            for (int m = 0; m < 2; m++) {
                const int ra = rg * 32 + m * 16 + (lane >> 2);
                const float* Sr = S + ra * TPAD + ks * 16 + (lane & 3) * 2;
                float2 p0 = *(const float2*)(Sr);
                float2 p1 = *(const float2*)(Sr + 8);
                float2 p2 = *(const float2*)(Sr + 8 * TPAD);
                float2 p3 = *(const float2*)(Sr + 8 * TPAD + 8);
                ahi[m][0] = bf16x2(p0.x, p0.y);
                ahi[m][1] = bf16x2(p2.x, p2.y);
                ahi[m][2] = bf16x2(p1.x, p1.y);
                ahi[m][3] = bf16x2(p3.x, p3.y);
                alo[m][0] = bf16x2(p0.x - bf_lo(ahi[m][0]), p0.y - bf_hi(ahi[m][0]));
                alo[m][1] = bf16x2(p2.x - bf_lo(ahi[m][1]), p2.y - bf_hi(ahi[m][1]));
                alo[m][2] = bf16x2(p1.x - bf_lo(ahi[m][2]), p1.y - bf_hi(ahi[m][2]));
                alo[m][3] = bf16x2(p3.x - bf_lo(ahi[m][3]), p3.y - bf_hi(ahi[m][3]));
            }
#pragma unroll
            for (int nt = 0; nt < 4; nt++) {
                const int bidx = (ks * 16 + cg * 4 + nt) * 32 + lane;
                uint2 bh = Bhi[bidx];
                uint2 bl = Blo[bidx];
#pragma unroll
                for (int m = 0; m < 2; m++) {
                    mma_bf16(acc[m][nt], ahi[m], bh);
                    mma_bf16(acc[m][nt], ahi[m], bl);
                    mma_bf16(acc[m][nt], alo[m], bh);
                }
            }
        }

        // ---- epilogue: STG.64 per (m, nt, row-half) ----
        float* ob = out + (size_t)rowbase * GD;
#pragma unroll
        for (int m = 0; m < 2; m++) {
            const int r0 = rg * 32 + m * 16 + (lane >> 2);
#pragma unroll
            for (int nt = 0; nt < 4; nt++) {
                const int c = cg * 32 + nt * 8 + (lane & 3) * 2;
                *(float2*)(ob + (size_t)r0 * GD + c) =
                    make_float2(acc[m][nt][0], acc[m][nt][1]);
                *(float2*)(ob + (size_t)(r0 + 8) * GD + c) =
                    make_float2(acc[m][nt][2], acc[m][nt][3]);
            }
        }
    }
}

// ---------------------------------------------------------------------------
extern "C" void kernel_launch(void* const* d_in, const int* in_sizes, int n_in,
                              void* d_out, int out_size) {
    const int*   archs    = (const int*)  d_in[0];
    const float* init_emb = (const float*)d_in[1];
    const float* op_emb   = (const float*)d_in[2];
    const float* xw       = (const float*)d_in[3];
    const float* xb       = (const float*)d_in[4];
    const float* w1       = (const float*)d_in[5];
    const float* w2       = (const float*)d_in[6];
    float* out = (float*)d_out;

    cudaFuncSetAttribute(gcn_main_kernel,
                         cudaFuncAttributeMaxDynamicSharedMemorySize, SMEM_BYTES);

    gcn_precompute_kernel<<<1, 128>>>(init_emb, op_emb, xw, xb, w1);
    w2_pack_kernel<<<16, 256>>>(w2);
    gcn_main_kernel<<<ROWS / TILE_M, 512, SMEM_BYTES>>>(archs, out);
}

// round 4
// speedup vs baseline: 1.8768x; 1.1189x over previous
#include <cuda_runtime.h>
#include <cuda_bf16.h>
#include <cstdint>

// ---------------------------------------------------------------------------
// GCNArchEmbedder via mma.sync bf16 (HMMA), 3-pass hi/lo fp32 emulation.
//   Prep (parallel): tables U0/U1/H1init/Uc + W2 fragment pack.
//   Phase 1: build A fragments (bf16 hi/lo, mma layout) directly in smem.
//   Phase 2: D = S @ W2 as Ahi*Bhi + Ahi*Blo + Alo*Bhi, m16n8k16 bf16 mma.
// ---------------------------------------------------------------------------

#define NUM_PRIM   8
#define OPD        48
#define OPH        48
#define GD         128
#define ROWS       65536
#define TILE_M     128
#define TPAD       132

// table rows: 0..7 U0[p], 8..15 U1[p], 16..17 H1init, 18 Uc (each 128 wide)
__device__ float g_tab[19 * GD];
// W2 fragments: idx = (ks*16 + ntile)*32 + lane ; {b0hi, b1hi, b0lo, b1lo}
__device__ uint4 g_bfrag[4096];

typedef unsigned long long ull;
__device__ __forceinline__ ull pk2(float lo, float hi) {
    ull r; asm("mov.b64 %0, {%1, %2};" : "=l"(r) : "f"(lo), "f"(hi)); return r;
}
__device__ __forceinline__ void unpk2(float& lo, float& hi, ull v) {
    asm("mov.b64 {%0, %1}, %2;" : "=f"(lo), "=f"(hi) : "l"(v));
}
__device__ __forceinline__ ull add2(ull a, ull b) {
    ull r; asm("add.rn.f32x2 %0, %1, %2;" : "=l"(r) : "l"(a), "l"(b)); return r;
}
__device__ __forceinline__ ull mul2(ull a, ull b) {
    ull r; asm("mul.rn.f32x2 %0, %1, %2;" : "=l"(r) : "l"(a), "l"(b)); return r;
}
__device__ __forceinline__ void fma2(ull& d, ull a, ull b) {
    asm("fma.rn.f32x2 %0, %1, %2, %0;" : "+l"(d) : "l"(a), "l"(b));
}
// low half = first arg (k-even element)
__device__ __forceinline__ uint32_t bf16x2(float lo, float hi) {
    uint32_t r; asm("cvt.rn.bf16x2.f32 %0, %1, %2;" : "=r"(r) : "f"(hi), "f"(lo)); return r;
}
__device__ __forceinline__ float bf_lo(uint32_t u) { return __uint_as_float(u << 16); }
__device__ __forceinline__ float bf_hi(uint32_t u) { return __uint_as_float(u & 0xffff0000u); }

__device__ __forceinline__ void mma_bf16(float* d, const uint32_t* a,
                                         uint32_t b0, uint32_t b1) {
    asm volatile(
        "mma.sync.aligned.m16n8k16.row.col.f32.bf16.bf16.f32 "
        "{%0,%1,%2,%3}, {%4,%5,%6,%7}, {%8,%9}, {%0,%1,%2,%3};"
        : "+f"(d[0]), "+f"(d[1]), "+f"(d[2]), "+f"(d[3])
        : "r"(a[0]), "r"(a[1]), "r"(a[2]), "r"(a[3]), "r"(b0), "r"(b1));
}

// ---------------------------------------------------------------------------
// Prep kernel, <<<25, 256>>>:
//   blocks 0..7 : U0[p], U1[p]       block 8 : H1init rows + Uc
//   blocks 9..24: W2 fragment pack
// ---------------------------------------------------------------------------
__global__ void gcn_prep_kernel(const float* __restrict__ init_emb,
                                const float* __restrict__ op_emb,
                                const float* __restrict__ xw,
                                const float* __restrict__ xb,
                                const float* __restrict__ w1,
                                const float* __restrict__ w2) {
    const int b = blockIdx.x;
    const int t = threadIdx.x;

    if (b < 8) {                       // primitive p = b
        __shared__ float T[2][OPH];
        if (t < 96) {
            const int which = t / 48, h = t % 48;
            float s0 = 0.f, s1 = 0.f;
            const int db = which * OPD;
            for (int d = 0; d < OPD; d += 2) {
                s0 = fmaf(op_emb[b * OPD + d],     xw[(db + d) * OPH + h],     s0);
                s1 = fmaf(op_emb[b * OPD + d + 1], xw[(db + d + 1) * OPH + h], s1);
            }
            T[which][h] = s0 + s1;
        }
        __syncthreads();
        const int which = t >> 7, f = t & 127;
        float s0 = 0.f, s1 = 0.f;
        for (int h = 0; h < OPH; h += 2) {
            s0 = fmaf(T[which][h],     w1[h * GD + f],       s0);
            s1 = fmaf(T[which][h + 1], w1[(h + 1) * GD + f], s1);
        }
        g_tab[(which * 8 + b) * GD + f] = s0 + s1;
    } else if (b == 8) {               // init rows + Uc
        __shared__ float Y[2][OPH];
        if (t < 96) {
            const int kk = t / 48, h = t % 48;
            float s0 = xb[h], s1 = 0.f;
            for (int d = 0; d < 2 * OPD; d += 2) {
                s0 = fmaf(init_emb[kk * 2 * OPD + d],     xw[d * OPH + h],       s0);
                s1 = fmaf(init_emb[kk * 2 * OPD + d + 1], xw[(d + 1) * OPH + h], s1);
            }
            Y[kk][h] = s0 + s1;
        }
        __syncthreads();
        const int kk = t >> 7, f = t & 127;
        float s0 = 0.f, s1 = 0.f;
        for (int h = 0; h < OPH; h += 2) {
            s0 = fmaf(Y[kk][h],     w1[h * GD + f],       s0);
            s1 = fmaf(Y[kk][h + 1], w1[(h + 1) * GD + f], s1);
        }
        g_tab[(16 + kk) * GD + f] = s0 + s1;
        if (kk == 0) {
            float c0 = 0.f, c1 = 0.f;
            for (int h = 0; h < OPH; h += 2) {
                c0 = fmaf(xb[h],     w1[h * GD + f],       c0);
                c1 = fmaf(xb[h + 1], w1[(h + 1) * GD + f], c1);
            }
            g_tab[18 * GD + f] = c0 + c1;
        }
    } else {                           // W2 pack
        const int idx = (b - 9) * 256 + t;   // 0..4095
        const int lane = idx & 31;
        const int nt   = (idx >> 5) & 15;
        const int ks   = idx >> 9;
        const int k0 = ks * 16 + (lane & 3) * 2;
        const int n  = nt * 8 + (lane >> 2);
        float w00 = w2[k0 * GD + n];
        float w01 = w2[(k0 + 1) * GD + n];
        float w10 = w2[(k0 + 8) * GD + n];
        float w11 = w2[(k0 + 9) * GD + n];
        uint32_t b0h = bf16x2(w00, w01);
        uint32_t b1h = bf16x2(w10, w11);
        uint32_t b0l = bf16x2(w00 - bf_lo(b0h), w01 - bf_hi(b0h));
        uint32_t b1l = bf16x2(w10 - bf_lo(b1h), w11 - bf_hi(b1h));
        g_bfrag[idx] = make_uint4(b0h, b1h, b0l, b1l);
    }
}

// ---------------------------------------------------------------------------
// Main kernel. smem byte layout:
//   AH   0       (32768)  [rg4][ks8][m2][pos32] uint4, XOR-swizzled pos
//   AL   32768   (32768)
//   B    65536   (65536)  [ks8][nt16][lane32] uint4 {b0h,b1h,b0l,b1l}
//   tab  131072  (10032)  19 x TPAD floats
//   arch 141104  (8192)
// total 149296 B
// ---------------------------------------------------------------------------
#define SM_AH    0
#define SM_AL    32768
#define SM_B     65536
#define SM_TAB   131072
#define SM_ARCH  141104
#define SMEM_BYTES 149296

__global__ void __launch_bounds__(512, 1)
gcn_main_kernel(const int* __restrict__ archs, float* __restrict__ out) {
    extern __shared__ char smem[];
    float* tab   = (float*)(smem + SM_TAB);
    int*  archsm = (int*)(smem + SM_ARCH);

    const int tid  = threadIdx.x;
    const int wid  = tid >> 5;
    const int lane = tid & 31;
    const int rowbase = blockIdx.x * TILE_M;

    // ---- stage B frags, tables, archs ----
    {
        uint4* dB = (uint4*)(smem + SM_B);
#pragma unroll
        for (int i = 0; i < 8; i++) dB[tid + 512 * i] = g_bfrag[tid + 512 * i];
        for (int idx = tid; idx < 19 * GD; idx += 512)
            tab[(idx >> 7) * TPAD + (idx & 127)] = g_tab[idx];
        const int4* av = (const int4*)archs + (size_t)rowbase * 4;
        ((int4*)archsm)[tid] = av[tid];
    }
    __syncthreads();

    // =======================================================================
    // Phase 1: per (row, kq) thread builds bf16 hi/lo A-fragments in smem.
    // =======================================================================
    {
        const int row = tid & 127;
        const int kq  = tid >> 7;          // ks in {2kq, 2kq+1}
        const int rg  = row >> 5;
        const int mm_ = (row >> 4) & 1;
        const int r   = row & 7;
        const bool hiRole = ((row & 8) == 0);

        const int* ar = archsm + row * 16;
        int pe[8], oe[8];
#pragma unroll
        for (int e = 0; e < 8; e++) { pe[e] = ar[e]; oe[e] = ar[8 + e]; }

        ull A2[4][6];
        float mmv[4];
#pragma unroll
        for (int s = 0; s < 4; s++) {
#pragma unroll
            for (int j = 0; j < 6; j++) {
                float v = (pe[2 * s] == j ? 1.f : 0.f) + (pe[2 * s + 1] == j ? 1.f : 0.f);
                A2[s][j] = pk2(v, v);
            }
            float c = 0.f;
#pragma unroll
            for (int e = 0; e < 8; e++) c += (pe[e] == s + 2) ? 1.f : 0.f;
            mmv[s] = c * 0.25f;
        }

        const float* qa0 = tab + oe[0] * TPAD;
        const float* qb0 = tab + (8 + oe[1]) * TPAD;
        const float* qa1 = tab + oe[2] * TPAD;
        const float* qb1 = tab + (8 + oe[3]) * TPAD;
        const float* qa2 = tab + oe[4] * TPAD;
        const float* qb2 = tab + (8 + oe[5]) * TPAD;
        const float* qa3 = tab + oe[6] * TPAD;
        const float* qb3 = tab + (8 + oe[7]) * TPAD;
        const float* p0 = tab + 16 * TPAD;
        const float* p1 = tab + 17 * TPAD;
        const float* pc = tab + 18 * TPAD;

        auto paircomp = [&](int k, uint32_t& hi2, uint32_t& lo2) {
            ull c  = *(const ull*)(pc + k);
            ull h0 = *(const ull*)(p0 + k);
            ull h1 = *(const ull*)(p1 + k);
            ull h2 = add2(add2(*(const ull*)(qa0 + k), *(const ull*)(qb0 + k)), c);
            ull h3 = add2(add2(*(const ull*)(qa1 + k), *(const ull*)(qb1 + k)), c);
            ull h4 = add2(add2(*(const ull*)(qa2 + k), *(const ull*)(qb2 + k)), c);
            ull h5 = add2(add2(*(const ull*)(qa3 + k), *(const ull*)(qb3 + k)), c);
            float a0 = 0.f, a1 = 0.f;
#pragma unroll
            for (int s = 0; s < 4; s++) {
                ull z = mul2(A2[s][0], h0);
                fma2(z, A2[s][1], h1);
                fma2(z, A2[s][2], h2);
                fma2(z, A2[s][3], h3);
                fma2(z, A2[s][4], h4);
                fma2(z, A2[s][5], h5);
                float zl, zh; unpk2(zl, zh, z);
                zl = fmaxf(zl, 0.f);
                zh = fmaxf(zh, 0.f);
                a0 = fmaf(mmv[s], zl, a0);
                a1 = fmaf(mmv[s], zh, a1);
            }
            hi2 = bf16x2(a0, a1);
            lo2 = bf16x2(a0 - bf_lo(hi2), a1 - bf_hi(hi2));
        };

#pragma unroll
        for (int kk = 0; kk < 2; kk++) {
            const int ks = kq * 2 + kk;
            char* slotH = smem + SM_AH + ((rg * 8 + ks) * 2 + mm_) * 512;
            char* slotL = smem + SM_AL + ((rg * 8 + ks) * 2 + mm_) * 512;
#pragma unroll
            for (int j = 0; j < 4; j++) {
                uint32_t hA, lA, hC, lC;
                paircomp(ks * 16 + 2 * j, hA, lA);
                paircomp(ks * 16 + 2 * j + 8, hC, lC);
                uint32_t ohA = __shfl_xor_sync(0xffffffffu, hA, 8);
                uint32_t ohC = __shfl_xor_sync(0xffffffffu, hC, 8);
                uint32_t olA = __shfl_xor_sync(0xffffffffu, lA, 8);
                uint32_t olC = __shfl_xor_sync(0xffffffffu, lC, 8);
                const int pos = r * 4 + (j ^ ((r >> 1) & 3));
                if (hiRole) {
                    *(uint4*)(slotH + pos * 16) = make_uint4(hA, ohA, hC, ohC);
                } else {
                    *(uint4*)(slotL + pos * 16) = make_uint4(olA, lA, olC, lC);
                }
            }
        }
    }
    __syncthreads();

    // =======================================================================
    // Phase 2: warp (rg, cg) = rows [32rg,+32) x cols [32cg,+32); 3-pass mma.
    // =======================================================================
    {
        const int rg = wid >> 2;
        const int cg = wid & 3;
        const int pos = (lane & 28) | ((lane ^ (lane >> 3)) & 3);

        float acc[2][4][4];
#pragma unroll
        for (int m = 0; m < 2; m++)
#pragma unroll
            for (int nt = 0; nt < 4; nt++)
#pragma unroll
                for (int j = 0; j < 4; j++) acc[m][nt][j] = 0.f;

#pragma unroll
        for (int ks = 0; ks < 8; ks++) {
            const uint4* AHp = (const uint4*)(smem + SM_AH + (rg * 8 + ks) * 1024);
            const uint4* ALp = (const uint4*)(smem + SM_AL + (rg * 8 + ks) * 1024);
            uint4 ah0 = AHp[pos];
            uint4 ah1 = AHp[32 + pos];
            uint4 al0 = ALp[pos];
            uint4 al1 = ALp[32 + pos];
            const uint4* Bp = (const uint4*)(smem + SM_B + (ks * 16 + cg * 4) * 512);
#pragma unroll
            for (int nt = 0; nt < 4; nt++) {
                uint4 B = Bp[nt * 32 + lane];
                mma_bf16(acc[0][nt], (const uint32_t*)&ah0, B.x, B.y);
                mma_bf16(acc[1][nt], (const uint32_t*)&ah1, B.x, B.y);
                mma_bf16(acc[0][nt], (const uint32_t*)&ah0, B.z, B.w);
                mma_bf16(acc[1][nt], (const uint32_t*)&ah1, B.z, B.w);
                mma_bf16(acc[0][nt], (const uint32_t*)&al0, B.x, B.y);
                mma_bf16(acc[1][nt], (const uint32_t*)&al1, B.x, B.y);
            }
        }

        // ---- epilogue ----
        float* ob = out + (size_t)rowbase * GD;
#pragma unroll
        for (int m = 0; m < 2; m++) {
            const int r0 = rg * 32 + m * 16 + (lane >> 2);
#pragma unroll
            for (int nt = 0; nt < 4; nt++) {
                const int c = cg * 32 + nt * 8 + (lane & 3) * 2;
                *(float2*)(ob + (size_t)r0 * GD + c) =
                    make_float2(acc[m][nt][0], acc[m][nt][1]);
                *(float2*)(ob + (size_t)(r0 + 8) * GD + c) =
                    make_float2(acc[m][nt][2], acc[m][nt][3]);
            }
        }
    }
}

// ---------------------------------------------------------------------------
extern "C" void kernel_launch(void* const* d_in, const int* in_sizes, int n_in,
                              void* d_out, int out_size) {
    const int*   archs    = (const int*)  d_in[0];
    const float* init_emb = (const float*)d_in[1];
    const float* op_emb   = (const float*)d_in[2];
    const float* xw       = (const float*)d_in[3];
    const float* xb       = (const float*)d_in[4];
    const float* w1       = (const float*)d_in[5];
    const float* w2       = (const float*)d_in[6];
    float* out = (float*)d_out;

    cudaFuncSetAttribute(gcn_main_kernel,
                         cudaFuncAttributeMaxDynamicSharedMemorySize, SMEM_BYTES);

    gcn_prep_kernel<<<25, 256>>>(init_emb, op_emb, xw, xb, w1, w2);
    gcn_main_kernel<<<ROWS / TILE_M, 512, SMEM_BYTES>>>(archs, out);
}

// round 5
// speedup vs baseline: 2.1181x; 1.1286x over previous
#include <cuda_runtime.h>
#include <cuda_bf16.h>
#include <cstdint>

// ---------------------------------------------------------------------------
// GCNArchEmbedder via mma.sync bf16 (HMMA), 3-pass hi/lo fp32 emulation.
// R5: TILE_M=64 / 256 threads -> 2 CTAs/SM; cp.async B staging; Uc folded.
// ---------------------------------------------------------------------------

#define NUM_PRIM   8
#define OPD        48
#define OPH        48
#define GD         128
#define ROWS       65536
#define TILE_M     64
#define TPAD       132

// table rows: 0..7 U0'[p], 8..15 U1'[p], 16..17 H1init  (each 128 wide)
__device__ float g_tab[18 * GD];
// W2 fragments: idx = (ks*16 + ntile)*32 + lane ; {b0hi, b1hi, b0lo, b1lo}
__device__ uint4 g_bfrag[4096];

typedef unsigned long long ull;
__device__ __forceinline__ ull pk2(float lo, float hi) {
    ull r; asm("mov.b64 %0, {%1, %2};" : "=l"(r) : "f"(lo), "f"(hi)); return r;
}
__device__ __forceinline__ void unpk2(float& lo, float& hi, ull v) {
    asm("mov.b64 {%0, %1}, %2;" : "=f"(lo), "=f"(hi) : "l"(v));
}
__device__ __forceinline__ ull add2(ull a, ull b) {
    ull r; asm("add.rn.f32x2 %0, %1, %2;" : "=l"(r) : "l"(a), "l"(b)); return r;
}
__device__ __forceinline__ ull mul2(ull a, ull b) {
    ull r; asm("mul.rn.f32x2 %0, %1, %2;" : "=l"(r) : "l"(a), "l"(b)); return r;
}
__device__ __forceinline__ void fma2(ull& d, ull a, ull b) {
    asm("fma.rn.f32x2 %0, %1, %2, %0;" : "+l"(d) : "l"(a), "l"(b));
}
// low half = first arg (k-even element)
__device__ __forceinline__ uint32_t bf16x2(float lo, float hi) {
    uint32_t r; asm("cvt.rn.bf16x2.f32 %0, %1, %2;" : "=r"(r) : "f"(hi), "f"(lo)); return r;
}
__device__ __forceinline__ float bf_lo(uint32_t u) { return __uint_as_float(u << 16); }
__device__ __forceinline__ float bf_hi(uint32_t u) { return __uint_as_float(u & 0xffff0000u); }

__device__ __forceinline__ void mma_bf16(float* d, const uint32_t* a,
                                         uint32_t b0, uint32_t b1) {
    asm volatile(
        "mma.sync.aligned.m16n8k16.row.col.f32.bf16.bf16.f32 "
        "{%0,%1,%2,%3}, {%4,%5,%6,%7}, {%8,%9}, {%0,%1,%2,%3};"
        : "+f"(d[0]), "+f"(d[1]), "+f"(d[2]), "+f"(d[3])
        : "r"(a[0]), "r"(a[1]), "r"(a[2]), "r"(a[3]), "r"(b0), "r"(b1));
}

__device__ __forceinline__ uint32_t smem_u32(const void* p) {
    uint32_t a;
    asm("{ .reg .u64 t; cvta.to.shared.u64 t, %1; cvt.u32.u64 %0, t; }" : "=r"(a) : "l"(p));
    return a;
}
__device__ __forceinline__ void cp_async16(uint32_t saddr, const void* g) {
    asm volatile("cp.async.cg.shared.global [%0], [%1], 16;" :: "r"(saddr), "l"(g) : "memory");
}

// ---------------------------------------------------------------------------
// Prep kernel, <<<25, 256>>>:
//   blocks 0..7 : U0'[p], U1'[p] (Uc/2 folded)    block 8 : H1init rows
//   blocks 9..24: W2 fragment pack
// ---------------------------------------------------------------------------
__global__ void gcn_prep_kernel(const float* __restrict__ init_emb,
                                const float* __restrict__ op_emb,
                                const float* __restrict__ xw,
                                const float* __restrict__ xb,
                                const float* __restrict__ w1,
                                const float* __restrict__ w2) {
    const int b = blockIdx.x;
    const int t = threadIdx.x;

    if (b < 8) {                       // primitive p = b
        __shared__ float T[2][OPH];
        if (t < 96) {
            const int which = t / 48, h = t % 48;
            float s0 = 0.f, s1 = 0.f;
            const int db = which * OPD;
            for (int d = 0; d < OPD; d += 2) {
                s0 = fmaf(op_emb[b * OPD + d],     xw[(db + d) * OPH + h],     s0);
                s1 = fmaf(op_emb[b * OPD + d + 1], xw[(db + d + 1) * OPH + h], s1);
            }
            T[which][h] = s0 + s1;
        }
        __syncthreads();
        const int which = t >> 7, f = t & 127;
        float s0 = 0.f, s1 = 0.f, uc = 0.f;
        for (int h = 0; h < OPH; h += 2) {
            float wa = w1[h * GD + f], wb = w1[(h + 1) * GD + f];
            s0 = fmaf(T[which][h],     wa, s0);
            s1 = fmaf(T[which][h + 1], wb, s1);
            uc = fmaf(xb[h], wa, fmaf(xb[h + 1], wb, uc));
        }
        g_tab[(which * 8 + b) * GD + f] = s0 + s1 + 0.5f * uc;
    } else if (b == 8) {               // init rows
        __shared__ float Y[2][OPH];
        if (t < 96) {
            const int kk = t / 48, h = t % 48;
            float s0 = xb[h], s1 = 0.f;
            for (int d = 0; d < 2 * OPD; d += 2) {
                s0 = fmaf(init_emb[kk * 2 * OPD + d],     xw[d * OPH + h],       s0);
                s1 = fmaf(init_emb[kk * 2 * OPD + d + 1], xw[(d + 1) * OPH + h], s1);
            }
            Y[kk][h] = s0 + s1;
        }
        __syncthreads();
        const int kk = t >> 7, f = t & 127;
        float s0 = 0.f, s1 = 0.f;
        for (int h = 0; h < OPH; h += 2) {
            s0 = fmaf(Y[kk][h],     w1[h * GD + f],       s0);
            s1 = fmaf(Y[kk][h + 1], w1[(h + 1) * GD + f], s1);
        }
        g_tab[(16 + kk) * GD + f] = s0 + s1;
    } else {                           // W2 pack
        const int idx = (b - 9) * 256 + t;   // 0..4095
        const int lane = idx & 31;
        const int nt   = (idx >> 5) & 15;
        const int ks   = idx >> 9;
        const int k0 = ks * 16 + (lane & 3) * 2;
        const int n  = nt * 8 + (lane >> 2);
        float w00 = w2[k0 * GD + n];
        float w01 = w2[(k0 + 1) * GD + n];
        float w10 = w2[(k0 + 8) * GD + n];
        float w11 = w2[(k0 + 9) * GD + n];
        uint32_t b0h = bf16x2(w00, w01);
        uint32_t b1h = bf16x2(w10, w11);
        uint32_t b0l = bf16x2(w00 - bf_lo(b0h), w01 - bf_hi(b0h));
        uint32_t b1l = bf16x2(w10 - bf_lo(b1h), w11 - bf_hi(b1h));
        g_bfrag[idx] = make_uint4(b0h, b1h, b0l, b1l);
    }
}

// ---------------------------------------------------------------------------
// Main kernel (TILE_M = 64, 256 threads, 2 CTAs/SM). smem byte layout:
//   AH   0       (16384)  [rg2][ks8][m2][pos32] uint4, XOR-swizzled pos
//   AL   16384   (16384)
//   B    32768   (65536)  [ks8][nt16][lane32] uint4 {b0h,b1h,b0l,b1l}
//   tab  98304   (9504)   18 x TPAD floats
//   arch 107808  (4096)
// total 111904 B
// ---------------------------------------------------------------------------
#define SM_AH    0
#define SM_AL    16384
#define SM_B     32768
#define SM_TAB   98304
#define SM_ARCH  107808
#define SMEM_BYTES 111904

__global__ void __launch_bounds__(256, 2)
gcn_main_kernel(const int* __restrict__ archs, float* __restrict__ out) {
    extern __shared__ char smem[];
    float* tab   = (float*)(smem + SM_TAB);
    int*  archsm = (int*)(smem + SM_ARCH);

    const int tid  = threadIdx.x;
    const int wid  = tid >> 5;
    const int lane = tid & 31;
    const int rowbase = blockIdx.x * TILE_M;

    // ---- B frags via cp.async (waited before phase 2) ----
    {
        const uint32_t bsm = smem_u32(smem + SM_B);
#pragma unroll
        for (int i = 0; i < 16; i++)
            cp_async16(bsm + (tid + 256 * i) * 16, &g_bfrag[tid + 256 * i]);
        asm volatile("cp.async.commit_group;" ::: "memory");
    }
    // ---- tables + archs (needed by phase 1) ----
    {
        for (int idx = tid; idx < 18 * GD; idx += 256)
            tab[(idx >> 7) * TPAD + (idx & 127)] = g_tab[idx];
        const int4* av = (const int4*)archs + (size_t)rowbase * 4;
        ((int4*)archsm)[tid] = av[tid];
    }
    __syncthreads();

    // =======================================================================
    // Phase 1: per (row, kq) thread builds bf16 hi/lo A-fragments in smem.
    // =======================================================================
    {
        const int row = tid & 63;
        const int kq  = tid >> 6;          // ks in {2kq, 2kq+1}
        const int rg  = row >> 5;
        const int mm_ = (row >> 4) & 1;
        const int r   = row & 7;
        const bool hiRole = ((row & 8) == 0);

        const int* ar = archsm + row * 16;
        int pe[8], oe[8];
#pragma unroll
        for (int e = 0; e < 8; e++) { pe[e] = ar[e]; oe[e] = ar[8 + e]; }

        ull A2[4][6];
        float mmv[4];
#pragma unroll
        for (int s = 0; s < 4; s++) {
#pragma unroll
            for (int j = 0; j < 6; j++) {
                float v = (pe[2 * s] == j ? 1.f : 0.f) + (pe[2 * s + 1] == j ? 1.f : 0.f);
                A2[s][j] = pk2(v, v);
            }
            float c = 0.f;
#pragma unroll
            for (int e = 0; e < 8; e++) c += (pe[e] == s + 2) ? 1.f : 0.f;
            mmv[s] = c * 0.25f;
        }

        const float* qa0 = tab + oe[0] * TPAD;
        const float* qb0 = tab + (8 + oe[1]) * TPAD;
        const float* qa1 = tab + oe[2] * TPAD;
        const float* qb1 = tab + (8 + oe[3]) * TPAD;
        const float* qa2 = tab + oe[4] * TPAD;
        const float* qb2 = tab + (8 + oe[5]) * TPAD;
        const float* qa3 = tab + oe[6] * TPAD;
        const float* qb3 = tab + (8 + oe[7]) * TPAD;
        const float* p0 = tab + 16 * TPAD;
        const float* p1 = tab + 17 * TPAD;

        auto paircomp = [&](int k, uint32_t& hi2, uint32_t& lo2) {
            ull h0 = *(const ull*)(p0 + k);
            ull h1 = *(const ull*)(p1 + k);
            ull h2 = add2(*(const ull*)(qa0 + k), *(const ull*)(qb0 + k));
            ull h3 = add2(*(const ull*)(qa1 + k), *(const ull*)(qb1 + k));
            ull h4 = add2(*(const ull*)(qa2 + k), *(const ull*)(qb2 + k));
            ull h5 = add2(*(const ull*)(qa3 + k), *(const ull*)(qb3 + k));
            float a0 = 0.f, a1 = 0.f;
#pragma unroll
            for (int s = 0; s < 4; s++) {
                ull z = mul2(A2[s][0], h0);
                fma2(z, A2[s][1], h1);
                fma2(z, A2[s][2], h2);
                fma2(z, A2[s][3], h3);
                fma2(z, A2[s][4], h4);
                fma2(z, A2[s][5], h5);
                float zl, zh; unpk2(zl, zh, z);
                zl = fmaxf(zl, 0.f);
                zh = fmaxf(zh, 0.f);
                a0 = fmaf(mmv[s], zl, a0);
                a1 = fmaf(mmv[s], zh, a1);
            }
            hi2 = bf16x2(a0, a1);
            lo2 = bf16x2(a0 - bf_lo(hi2), a1 - bf_hi(hi2));
        };

#pragma unroll
        for (int kk = 0; kk < 2; kk++) {
            const int ks = kq * 2 + kk;
            char* slotH = smem + SM_AH + ((rg * 8 + ks) * 2 + mm_) * 512;
            char* slotL = smem + SM_AL + ((rg * 8 + ks) * 2 + mm_) * 512;
#pragma unroll
            for (int j = 0; j < 4; j++) {
                uint32_t hA, lA, hC, lC;
                paircomp(ks * 16 + 2 * j, hA, lA);
                paircomp(ks * 16 + 2 * j + 8, hC, lC);
                uint32_t ohA = __shfl_xor_sync(0xffffffffu, hA, 8);
                uint32_t ohC = __shfl_xor_sync(0xffffffffu, hC, 8);
                uint32_t olA = __shfl_xor_sync(0xffffffffu, lA, 8);
                uint32_t olC = __shfl_xor_sync(0xffffffffu, lC, 8);
                const int pos = r * 4 + (j ^ ((r >> 1) & 3));
                if (hiRole) {
                    *(uint4*)(slotH + pos * 16) = make_uint4(hA, ohA, hC, ohC);
                } else {
                    *(uint4*)(slotL + pos * 16) = make_uint4(olA, lA, olC, lC);
                }
            }
        }
    }
    asm volatile("cp.async.wait_group 0;" ::: "memory");
    __syncthreads();

    // =======================================================================
    // Phase 2: warp (rg, cg) = rows [32rg,+32) x cols [32cg,+32); 3-pass mma.
    // =======================================================================
    {
        const int rg = wid >> 2;
        const int cg = wid & 3;
        const int pos = (lane & 28) | ((lane ^ (lane >> 3)) & 3);

        float acc[2][4][4];
#pragma unroll
        for (int m = 0; m < 2; m++)
#pragma unroll
            for (int nt = 0; nt < 4; nt++)
#pragma unroll
                for (int j = 0; j < 4; j++) acc[m][nt][j] = 0.f;

#pragma unroll
        for (int ks = 0; ks < 8; ks++) {
            const uint4* AHp = (const uint4*)(smem + SM_AH + (rg * 8 + ks) * 1024);
            const uint4* ALp = (const uint4*)(smem + SM_AL + (rg * 8 + ks) * 1024);
            uint4 ah0 = AHp[pos];
            uint4 ah1 = AHp[32 + pos];
            uint4 al0 = ALp[pos];
            uint4 al1 = ALp[32 + pos];
            const uint4* Bp = (const uint4*)(smem + SM_B + (ks * 16 + cg * 4) * 512);
#pragma unroll
            for (int nt = 0; nt < 4; nt++) {
                uint4 B = Bp[nt * 32 + lane];
                mma_bf16(acc[0][nt], (const uint32_t*)&ah0, B.x, B.y);
                mma_bf16(acc[1][nt], (const uint32_t*)&ah1, B.x, B.y);
                mma_bf16(acc[0][nt], (const uint32_t*)&ah0, B.z, B.w);
                mma_bf16(acc[1][nt], (const uint32_t*)&ah1, B.z, B.w);
                mma_bf16(acc[0][nt], (const uint32_t*)&al0, B.x, B.y);
                mma_bf16(acc[1][nt], (const uint32_t*)&al1, B.x, B.y);
            }
        }

        // ---- epilogue ----
        float* ob = out + (size_t)rowbase * GD;
#pragma unroll
        for (int m = 0; m < 2; m++) {
            const int r0 = rg * 32 + m * 16 + (lane >> 2);
#pragma unroll
            for (int nt = 0; nt < 4; nt++) {
                const int c = cg * 32 + nt * 8 + (lane & 3) * 2;
                *(float2*)(ob + (size_t)r0 * GD + c) =
                    make_float2(acc[m][nt][0], acc[m][nt][1]);
                *(float2*)(ob + (size_t)(r0 + 8) * GD + c) =
                    make_float2(acc[m][nt][2], acc[m][nt][3]);
            }
        }
    }
}

// ---------------------------------------------------------------------------
extern "C" void kernel_launch(void* const* d_in, const int* in_sizes, int n_in,
                              void* d_out, int out_size) {
    const int*   archs    = (const int*)  d_in[0];
    const float* init_emb = (const float*)d_in[1];
    const float* op_emb   = (const float*)d_in[2];
    const float* xw       = (const float*)d_in[3];
    const float* xb       = (const float*)d_in[4];
    const float* w1       = (const float*)d_in[5];
    const float* w2       = (const float*)d_in[6];
    float* out = (float*)d_out;

    cudaFuncSetAttribute(gcn_main_kernel,
                         cudaFuncAttributeMaxDynamicSharedMemorySize, SMEM_BYTES);

    gcn_prep_kernel<<<25, 256>>>(init_emb, op_emb, xw, xb, w1, w2);
    gcn_main_kernel<<<ROWS / TILE_M, 256, SMEM_BYTES>>>(archs, out);
}

// round 6
// speedup vs baseline: 2.1300x; 1.0056x over previous
#include <cuda_runtime.h>
#include <cuda_bf16.h>
#include <cstdint>

// ---------------------------------------------------------------------------
// GCNArchEmbedder via mma.sync bf16 (HMMA), 3-pass hi/lo fp32 emulation.
// R6: 512 threads / TILE_M=64 / <=64 regs -> 32 warps per SM (2 CTAs).
// ---------------------------------------------------------------------------

#define NUM_PRIM   8
#define OPD        48
#define OPH        48
#define GD         128
#define ROWS       65536
#define TILE_M     64
#define TPAD       132

// table rows: 0..7 U0'[p], 8..15 U1'[p], 16..17 H1init  (each 128 wide)
__device__ float g_tab[18 * GD];
// W2 fragments: idx = (ks*16 + ntile)*32 + lane ; {b0hi, b1hi, b0lo, b1lo}
__device__ uint4 g_bfrag[4096];

typedef unsigned long long ull;
__device__ __forceinline__ ull pk2(float lo, float hi) {
    ull r; asm("mov.b64 %0, {%1, %2};" : "=l"(r) : "f"(lo), "f"(hi)); return r;
}
__device__ __forceinline__ void unpk2(float& lo, float& hi, ull v) {
    asm("mov.b64 {%0, %1}, %2;" : "=f"(lo), "=f"(hi) : "l"(v));
}
__device__ __forceinline__ ull add2(ull a, ull b) {
    ull r; asm("add.rn.f32x2 %0, %1, %2;" : "=l"(r) : "l"(a), "l"(b)); return r;
}
__device__ __forceinline__ ull mul2(ull a, ull b) {
    ull r; asm("mul.rn.f32x2 %0, %1, %2;" : "=l"(r) : "l"(a), "l"(b)); return r;
}
__device__ __forceinline__ void fma2(ull& d, ull a, ull b) {
    asm("fma.rn.f32x2 %0, %1, %2, %0;" : "+l"(d) : "l"(a), "l"(b));
}
// low half = first arg (k-even element)
__device__ __forceinline__ uint32_t bf16x2(float lo, float hi) {
    uint32_t r; asm("cvt.rn.bf16x2.f32 %0, %1, %2;" : "=r"(r) : "f"(hi), "f"(lo)); return r;
}
__device__ __forceinline__ float bf_lo(uint32_t u) { return __uint_as_float(u << 16); }
__device__ __forceinline__ float bf_hi(uint32_t u) { return __uint_as_float(u & 0xffff0000u); }

__device__ __forceinline__ void mma_bf16(float* d, const uint32_t* a,
                                         uint32_t b0, uint32_t b1) {
    asm volatile(
        "mma.sync.aligned.m16n8k16.row.col.f32.bf16.bf16.f32 "
        "{%0,%1,%2,%3}, {%4,%5,%6,%7}, {%8,%9}, {%0,%1,%2,%3};"
        : "+f"(d[0]), "+f"(d[1]), "+f"(d[2]), "+f"(d[3])
        : "r"(a[0]), "r"(a[1]), "r"(a[2]), "r"(a[3]), "r"(b0), "r"(b1));
}

__device__ __forceinline__ uint32_t smem_u32(const void* p) {
    uint32_t a;
    asm("{ .reg .u64 t; cvta.to.shared.u64 t, %1; cvt.u32.u64 %0, t; }" : "=r"(a) : "l"(p));
    return a;
}
__device__ __forceinline__ void cp_async16(uint32_t saddr, const void* g) {
    asm volatile("cp.async.cg.shared.global [%0], [%1], 16;" :: "r"(saddr), "l"(g) : "memory");
}

// ---------------------------------------------------------------------------
// Prep kernel, <<<25, 256>>>:
//   blocks 0..7 : U0'[p], U1'[p] (Uc/2 folded)    block 8 : H1init rows
//   blocks 9..24: W2 fragment pack
// ---------------------------------------------------------------------------
__global__ void gcn_prep_kernel(const float* __restrict__ init_emb,
                                const float* __restrict__ op_emb,
                                const float* __restrict__ xw,
                                const float* __restrict__ xb,
                                const float* __restrict__ w1,
                                const float* __restrict__ w2) {
    const int b = blockIdx.x;
    const int t = threadIdx.x;

    if (b < 8) {                       // primitive p = b
        __shared__ float T[2][OPH];
        if (t < 96) {
            const int which = t / 48, h = t % 48;
            float s0 = 0.f, s1 = 0.f;
            const int db = which * OPD;
            for (int d = 0; d < OPD; d += 2) {
                s0 = fmaf(op_emb[b * OPD + d],     xw[(db + d) * OPH + h],     s0);
                s1 = fmaf(op_emb[b * OPD + d + 1], xw[(db + d + 1) * OPH + h], s1);
            }
            T[which][h] = s0 + s1;
        }
        __syncthreads();
        const int which = t >> 7, f = t & 127;
        float s0 = 0.f, s1 = 0.f, uc = 0.f;
        for (int h = 0; h < OPH; h += 2) {
            float wa = w1[h * GD + f], wb = w1[(h + 1) * GD + f];
            s0 = fmaf(T[which][h],     wa, s0);
            s1 = fmaf(T[which][h + 1], wb, s1);
            uc = fmaf(xb[h], wa, fmaf(xb[h + 1], wb, uc));
        }
        g_tab[(which * 8 + b) * GD + f] = s0 + s1 + 0.5f * uc;
    } else if (b == 8) {               // init rows
        __shared__ float Y[2][OPH];
        if (t < 96) {
            const int kk = t / 48, h = t % 48;
            float s0 = xb[h], s1 = 0.f;
            for (int d = 0; d < 2 * OPD; d += 2) {
                s0 = fmaf(init_emb[kk * 2 * OPD + d],     xw[d * OPH + h],       s0);
                s1 = fmaf(init_emb[kk * 2 * OPD + d + 1], xw[(d + 1) * OPH + h], s1);
            }
            Y[kk][h] = s0 + s1;
        }
        __syncthreads();
        const int kk = t >> 7, f = t & 127;
        float s0 = 0.f, s1 = 0.f;
        for (int h = 0; h < OPH; h += 2) {
            s0 = fmaf(Y[kk][h],     w1[h * GD + f],       s0);
            s1 = fmaf(Y[kk][h + 1], w1[(h + 1) * GD + f], s1);
        }
        g_tab[(16 + kk) * GD + f] = s0 + s1;
    } else {                           // W2 pack
        const int idx = (b - 9) * 256 + t;   // 0..4095
        const int lane = idx & 31;
        const int nt   = (idx >> 5) & 15;
        const int ks   = idx >> 9;
        const int k0 = ks * 16 + (lane & 3) * 2;
        const int n  = nt * 8 + (lane >> 2);
        float w00 = w2[k0 * GD + n];
        float w01 = w2[(k0 + 1) * GD + n];
        float w10 = w2[(k0 + 8) * GD + n];
        float w11 = w2[(k0 + 9) * GD + n];
        uint32_t b0h = bf16x2(w00, w01);
        uint32_t b1h = bf16x2(w10, w11);
        uint32_t b0l = bf16x2(w00 - bf_lo(b0h), w01 - bf_hi(b0h));
        uint32_t b1l = bf16x2(w10 - bf_lo(b1h), w11 - bf_hi(b1h));
        g_bfrag[idx] = make_uint4(b0h, b1h, b0l, b1l);
    }
}

// ---------------------------------------------------------------------------
// Main kernel (TILE_M = 64, 512 threads, 2 CTAs/SM). smem byte layout:
//   AH   0       (16384)  [g4][ks8][pos32] uint4, XOR-swizzled pos
//   AL   16384   (16384)
//   B    32768   (65536)  [ks8][nt16][lane32] uint4 {b0h,b1h,b0l,b1l}
//   tab  98304   (9504)   18 x TPAD floats
//   arch 107808  (4096)
// total 111904 B
// ---------------------------------------------------------------------------
#define SM_AH    0
#define SM_AL    16384
#define SM_B     32768
#define SM_TAB   98304
#define SM_ARCH  107808
#define SMEM_BYTES 111904

__global__ void __launch_bounds__(512, 2)
gcn_main_kernel(const int* __restrict__ archs, float* __restrict__ out) {
    extern __shared__ char smem[];
    float* tab   = (float*)(smem + SM_TAB);
    int*  archsm = (int*)(smem + SM_ARCH);

    const int tid  = threadIdx.x;
    const int wid  = tid >> 5;
    const int lane = tid & 31;
    const int rowbase = blockIdx.x * TILE_M;

    // ---- B frags via cp.async (waited before phase 2) ----
    {
        const uint32_t bsm = smem_u32(smem + SM_B);
#pragma unroll
        for (int i = 0; i < 8; i++)
            cp_async16(bsm + (tid + 512 * i) * 16, &g_bfrag[tid + 512 * i]);
        asm volatile("cp.async.commit_group;" ::: "memory");
    }
    // ---- tables + archs (needed by phase 1) ----
    {
        for (int idx = tid; idx < 18 * GD; idx += 512)
            tab[(idx >> 7) * TPAD + (idx & 127)] = g_tab[idx];
        if (tid < 256) {
            const int4* av = (const int4*)archs + (size_t)rowbase * 4;
            ((int4*)archsm)[tid] = av[tid];
        }
    }
    __syncthreads();

    // =======================================================================
    // Phase 1: thread (row, ks) builds bf16 hi/lo A-fragments in smem.
    // A coefficients kept as 24 floats; packed to f32x2 at point of use.
    // =======================================================================
    {
        const int row = tid & 63;
        const int ks  = tid >> 6;          // 0..7
        const int g_  = row >> 4;
        const int r   = row & 7;
        const bool hiRole = ((row & 8) == 0);

        const int* ar = archsm + row * 16;
        int pe[8], oe[8];
#pragma unroll
        for (int e = 0; e < 8; e++) { pe[e] = ar[e]; oe[e] = ar[8 + e]; }

        float Af[4][6];
        float mmv[4];
#pragma unroll
        for (int s = 0; s < 4; s++) {
#pragma unroll
            for (int j = 0; j < 6; j++)
                Af[s][j] = (pe[2 * s] == j ? 1.f : 0.f) + (pe[2 * s + 1] == j ? 1.f : 0.f);
            float c = 0.f;
#pragma unroll
            for (int e = 0; e < 8; e++) c += (pe[e] == s + 2) ? 1.f : 0.f;
            mmv[s] = c * 0.25f;
        }

        const float* qa0 = tab + oe[0] * TPAD;
        const float* qb0 = tab + (8 + oe[1]) * TPAD;
        const float* qa1 = tab + oe[2] * TPAD;
        const float* qb1 = tab + (8 + oe[3]) * TPAD;
        const float* qa2 = tab + oe[4] * TPAD;
        const float* qb2 = tab + (8 + oe[5]) * TPAD;
        const float* qa3 = tab + oe[6] * TPAD;
        const float* qb3 = tab + (8 + oe[7]) * TPAD;
        const float* p0 = tab + 16 * TPAD;
        const float* p1 = tab + 17 * TPAD;

        auto paircomp = [&](int k, uint32_t& hi2, uint32_t& lo2) {
            ull h0 = *(const ull*)(p0 + k);
            ull h1 = *(const ull*)(p1 + k);
            ull h2 = add2(*(const ull*)(qa0 + k), *(const ull*)(qb0 + k));
            ull h3 = add2(*(const ull*)(qa1 + k), *(const ull*)(qb1 + k));
            ull h4 = add2(*(const ull*)(qa2 + k), *(const ull*)(qb2 + k));
            ull h5 = add2(*(const ull*)(qa3 + k), *(const ull*)(qb3 + k));
            float a0 = 0.f, a1 = 0.f;
#pragma unroll
            for (int s = 0; s < 4; s++) {
                ull z = mul2(pk2(Af[s][0], Af[s][0]), h0);
                fma2(z, pk2(Af[s][1], Af[s][1]), h1);
                fma2(z, pk2(Af[s][2], Af[s][2]), h2);
                fma2(z, pk2(Af[s][3], Af[s][3]), h3);
                fma2(z, pk2(Af[s][4], Af[s][4]), h4);
                fma2(z, pk2(Af[s][5], Af[s][5]), h5);
                float zl, zh; unpk2(zl, zh, z);
                zl = fmaxf(zl, 0.f);
                zh = fmaxf(zh, 0.f);
                a0 = fmaf(mmv[s], zl, a0);
                a1 = fmaf(mmv[s], zh, a1);
            }
            hi2 = bf16x2(a0, a1);
            lo2 = bf16x2(a0 - bf_lo(hi2), a1 - bf_hi(hi2));
        };

        char* slotH = smem + SM_AH + (g_ * 8 + ks) * 512;
        char* slotL = smem + SM_AL + (g_ * 8 + ks) * 512;
#pragma unroll
        for (int j = 0; j < 4; j++) {
            uint32_t hA, lA, hC, lC;
            paircomp(ks * 16 + 2 * j, hA, lA);
            paircomp(ks * 16 + 2 * j + 8, hC, lC);
            uint32_t ohA = __shfl_xor_sync(0xffffffffu, hA, 8);
            uint32_t ohC = __shfl_xor_sync(0xffffffffu, hC, 8);
            uint32_t olA = __shfl_xor_sync(0xffffffffu, lA, 8);
            uint32_t olC = __shfl_xor_sync(0xffffffffu, lC, 8);
            const int pos = r * 4 + (j ^ ((r >> 1) & 3));
            if (hiRole) {
                *(uint4*)(slotH + pos * 16) = make_uint4(hA, ohA, hC, ohC);
            } else {
                *(uint4*)(slotL + pos * 16) = make_uint4(olA, lA, olC, lC);
            }
        }
    }
    asm volatile("cp.async.wait_group 0;" ::: "memory");
    __syncthreads();

    // =======================================================================
    // Phase 2: warp (rg, cg) = rows [16rg,+16) x cols [32cg,+32); 3-pass mma.
    // =======================================================================
    {
        const int rg = wid >> 2;
        const int cg = wid & 3;
        const int pos = (lane & 28) | ((lane ^ (lane >> 3)) & 3);

        float acc[4][4];
#pragma unroll
        for (int nt = 0; nt < 4; nt++)
#pragma unroll
            for (int j = 0; j < 4; j++) acc[nt][j] = 0.f;

#pragma unroll
        for (int ks = 0; ks < 8; ks++) {
            const uint4* AHp = (const uint4*)(smem + SM_AH + (rg * 8 + ks) * 512);
            const uint4* ALp = (const uint4*)(smem + SM_AL + (rg * 8 + ks) * 512);
            uint4 ah = AHp[pos];
            uint4 al = ALp[pos];
            const uint4* Bp = (const uint4*)(smem + SM_B + (ks * 16 + cg * 4) * 512);
#pragma unroll
            for (int nt = 0; nt < 4; nt++) {
                uint4 B = Bp[nt * 32 + lane];
                mma_bf16(acc[nt], (const uint32_t*)&ah, B.x, B.y);
                mma_bf16(acc[nt], (const uint32_t*)&ah, B.z, B.w);
                mma_bf16(acc[nt], (const uint32_t*)&al, B.x, B.y);
            }
        }

        // ---- epilogue ----
        float* ob = out + (size_t)rowbase * GD;
        const int r0 = rg * 16 + (lane >> 2);
#pragma unroll
        for (int nt = 0; nt < 4; nt++) {
            const int c = cg * 32 + nt * 8 + (lane & 3) * 2;
            *(float2*)(ob + (size_t)r0 * GD + c) = make_float2(acc[nt][0], acc[nt][1]);
            *(float2*)(ob + (size_t)(r0 + 8) * GD + c) = make_float2(acc[nt][2], acc[nt][3]);
        }
    }
}

// ---------------------------------------------------------------------------
extern "C" void kernel_launch(void* const* d_in, const int* in_sizes, int n_in,
                              void* d_out, int out_size) {
    const int*   archs    = (const int*)  d_in[0];
    const float* init_emb = (const float*)d_in[1];
    const float* op_emb   = (const float*)d_in[2];
    const float* xw       = (const float*)d_in[3];
    const float* xb       = (const float*)d_in[4];
    const float* w1       = (const float*)d_in[5];
    const float* w2       = (const float*)d_in[6];
    float* out = (float*)d_out;

    cudaFuncSetAttribute(gcn_main_kernel,
                         cudaFuncAttributeMaxDynamicSharedMemorySize, SMEM_BYTES);

    gcn_prep_kernel<<<25, 256>>>(init_emb, op_emb, xw, xb, w1, w2);
    gcn_main_kernel<<<ROWS / TILE_M, 512, SMEM_BYTES>>>(archs, out);
}